// round 15
// baseline (speedup 1.0000x reference)
#include <cuda_runtime.h>
#include <cuda_bf16.h>
#include <cuda_fp16.h>
#include <math.h>
#include <stdint.h>

#define BB 64
#define TT 20
#define EE 512
#define VV 32000
#define G4 2048   // 4*EE
#define NSTEP (TT - 1)

// ---------------- scratch (no allocations allowed) ----------------
__device__ float g_c[BB * EE];
__device__ float g_xgates[NSTEP * BB * G4];      // [(t-1)*64+b][4E]
__device__ unsigned g_bars[64];                  // grid-barrier slots (zeroed per call)
__device__ __nv_bfloat16 g_Hhi[BB * EE];         // h split [b][e] (recurrent A operand)
__device__ __nv_bfloat16 g_Hlo[BB * EE];
__device__ __nv_bfloat16 g_Ehi[TT * BB * EE];    // emb split [t*64+b][e]
__device__ __nv_bfloat16 g_Elo[TT * BB * EE];
__device__ __nv_bfloat16 g_WihHi[G4 * EE];
__device__ __nv_bfloat16 g_WihLo[G4 * EE];
__device__ __nv_bfloat16 g_WhhHi[G4 * EE];
__device__ __nv_bfloat16 g_WhhLo[G4 * EE];
__device__ __half g_SeqH[BB * TT * EE];          // fp16 seq [b*20+t][e] (proj A)
__device__ __half g_WoutH[(size_t)VV * EE];      // fp16 W_out (proj B)

// ================= helpers =================
__device__ __forceinline__ uint32_t smem_u32(const void* p) {
    uint32_t a;
    asm("{ .reg .u64 t; cvta.to.shared.u64 t, %1; cvt.u32.u64 %0, t; }" : "=r"(a) : "l"(p));
    return a;
}
__device__ __forceinline__ void bf16_split(float v, __nv_bfloat16& h, __nv_bfloat16& l) {
    h = __float2bfloat16(v);
    l = __float2bfloat16(v - __bfloat162float(h));
}

#define LDSM4(r, a)                                                            \
    asm volatile("ldmatrix.sync.aligned.m8n8.x4.shared.b16 {%0,%1,%2,%3}, [%4];" \
        : "=r"((r)[0]), "=r"((r)[1]), "=r"((r)[2]), "=r"((r)[3]) : "r"(a))
#define LDSM2(r, a)                                                            \
    asm volatile("ldmatrix.sync.aligned.m8n8.x2.shared.b16 {%0,%1}, [%2];"     \
        : "=r"((r)[0]), "=r"((r)[1]) : "r"(a))
#define MMA_BF16(acc, a, b)                                                    \
    asm volatile("mma.sync.aligned.m16n8k16.row.col.f32.bf16.bf16.f32 "        \
        "{%0,%1,%2,%3}, {%4,%5,%6,%7}, {%8,%9}, {%0,%1,%2,%3};"                \
        : "+f"((acc)[0]), "+f"((acc)[1]), "+f"((acc)[2]), "+f"((acc)[3])       \
        : "r"((a)[0]), "r"((a)[1]), "r"((a)[2]), "r"((a)[3]),                  \
          "r"((b)[0]), "r"((b)[1]))
#define MMA_F16(acc, a, b)                                                     \
    asm volatile("mma.sync.aligned.m16n8k16.row.col.f32.f16.f16.f32 "          \
        "{%0,%1,%2,%3}, {%4,%5,%6,%7}, {%8,%9}, {%0,%1,%2,%3};"                \
        : "+f"((acc)[0]), "+f"((acc)[1]), "+f"((acc)[2]), "+f"((acc)[3])       \
        : "r"((a)[0]), "r"((a)[1]), "r"((a)[2]), "r"((a)[3]),                  \
          "r"((b)[0]), "r"((b)[1]))
#define CP_ASYNC16(sp, gp)                                                     \
    asm volatile("cp.async.cg.shared.global [%0], [%1], 16;" :: "r"(sp), "l"(gp))

// ================= bf16-split HMMA GEMM (LSTM x-gates only) =================
#define BK 32
#define SRW 80
#define A_OP (128 * SRW)
#define B_OP (256 * SRW)
#define STAGEB (2 * A_OP + 2 * B_OP)  // 61440
#define SMEMB (2 * STAGEB)            // 122880

__global__ __launch_bounds__(256, 1) void hmma_gemm_kernel(
        const __nv_bfloat16* __restrict__ Ahi, const __nv_bfloat16* __restrict__ Alo,
        const __nv_bfloat16* __restrict__ Bhi, const __nv_bfloat16* __restrict__ Blo,
        float* __restrict__ C, int ldc,
        const float* __restrict__ bias1, const float* __restrict__ bias2, int mrows) {
    extern __shared__ char smem[];
    uint32_t sb = smem_u32(smem);
    int tid = threadIdx.x, lane = tid & 31, wid = tid >> 5;
    int wm = (wid & 1) * 64;
    int wn = (wid >> 1) * 64;
    int m0 = blockIdx.x * 128;
    int n0 = blockIdx.y * 256;

    float acc[4][8][4];
#pragma unroll
    for (int i = 0; i < 4; i++)
#pragma unroll
        for (int j = 0; j < 8; j++)
#pragma unroll
            for (int k = 0; k < 4; k++) acc[i][j][k] = 0.f;

#define LOAD_CHUNK(kc, buf)                                                          \
    do {                                                                             \
        _Pragma("unroll")                                                            \
        for (int i_ = 0; i_ < 12; i_++) {                                            \
            int u_ = tid + i_ * 256;                                                 \
            const __nv_bfloat16* src_;                                               \
            uint32_t sp_;                                                            \
            int grow_, c_;                                                           \
            if (u_ < 1024) {                                                         \
                int op_ = u_ >> 9;                                                   \
                int q_ = u_ & 511;                                                   \
                int r_ = q_ >> 2;                                                    \
                c_ = q_ & 3;                                                         \
                src_ = op_ ? Alo : Ahi;                                              \
                grow_ = m0 + r_;                                                     \
                sp_ = sb + (buf) * STAGEB + op_ * A_OP + r_ * SRW + c_ * 16;         \
            } else {                                                                 \
                int v_ = u_ - 1024;                                                  \
                int op_ = v_ >> 10;                                                  \
                int q_ = v_ & 1023;                                                  \
                int r_ = q_ >> 2;                                                    \
                c_ = q_ & 3;                                                         \
                src_ = op_ ? Blo : Bhi;                                              \
                grow_ = n0 + r_;                                                     \
                sp_ = sb + (buf) * STAGEB + 2 * A_OP + op_ * B_OP + r_ * SRW + c_ * 16; \
            }                                                                        \
            const void* gp_ = src_ + (size_t)grow_ * EE + (kc) * BK + c_ * 8;        \
            CP_ASYNC16(sp_, gp_);                                                    \
        }                                                                            \
        asm volatile("cp.async.commit_group;");                                      \
    } while (0)

    LOAD_CHUNK(0, 0);

    for (int kc = 0; kc < 16; kc++) {
        int buf = kc & 1;
        if (kc < 15) {
            LOAD_CHUNK(kc + 1, buf ^ 1);
            asm volatile("cp.async.wait_group 1;");
        } else {
            asm volatile("cp.async.wait_group 0;");
        }
        __syncthreads();

        uint32_t base = sb + buf * STAGEB;
#pragma unroll
        for (int ks = 0; ks < 2; ks++) {
            int kk = ks * 32;
            uint32_t ah[4][4], al[4][4];
#pragma unroll
            for (int mi = 0; mi < 4; mi++) {
                uint32_t ra = base + (uint32_t)(wm + mi * 16 + (lane & 15)) * SRW
                            + kk + ((lane >> 4) << 4);
                LDSM4(ah[mi], ra);
                LDSM4(al[mi], ra + A_OP);
            }
#pragma unroll
            for (int ni = 0; ni < 8; ni++) {
                uint32_t rb = base + 2 * A_OP
                            + (uint32_t)(wn + ni * 8 + (lane & 7)) * SRW
                            + kk + (((lane >> 3) & 1) << 4);
                uint32_t bh[2], bl[2];
                LDSM2(bh, rb);
                LDSM2(bl, rb + B_OP);
#pragma unroll
                for (int mi = 0; mi < 4; mi++) MMA_BF16(acc[mi][ni], ah[mi], bh);
#pragma unroll
                for (int mi = 0; mi < 4; mi++) MMA_BF16(acc[mi][ni], ah[mi], bl);
#pragma unroll
                for (int mi = 0; mi < 4; mi++) MMA_BF16(acc[mi][ni], al[mi], bh);
            }
        }
        __syncthreads();
    }

#pragma unroll
    for (int ni = 0; ni < 8; ni++) {
        int c0 = n0 + wn + ni * 8 + (lane & 3) * 2;
        float b0 = bias1[c0], b1 = bias1[c0 + 1];
        if (bias2) { b0 += bias2[c0]; b1 += bias2[c0 + 1]; }
#pragma unroll
        for (int mi = 0; mi < 4; mi++) {
            int r0 = m0 + wm + mi * 16 + (lane >> 2);
            float* p = C + (size_t)r0 * ldc + c0;
            if (r0 < mrows) {
                float2 v = make_float2(acc[mi][ni][0] + b0, acc[mi][ni][1] + b1);
                *(float2*)p = v;
            }
            if (r0 + 8 < mrows) {
                float2 v = make_float2(acc[mi][ni][2] + b0, acc[mi][ni][3] + b1);
                *(float2*)(p + (size_t)8 * ldc) = v;
            }
        }
    }
}

// ================= fp16 single-product GEMM (projection) =================
#define AH_OP (128 * SRW)            // 10240
#define BH_OP (256 * SRW)            // 20480
#define STH (AH_OP + BH_OP)          // 30720
#define SMH (2 * STH)                // 61440

__global__ __launch_bounds__(256, 1) void hf16_gemm_kernel(
        const __half* __restrict__ A, const __half* __restrict__ B,
        float* __restrict__ C, const float* __restrict__ bias) {
    extern __shared__ char smem[];
    uint32_t sb = smem_u32(smem);
    int tid = threadIdx.x, lane = tid & 31, wid = tid >> 5;
    int wm = (wid & 1) * 64;
    int wn = (wid >> 1) * 64;
    int m0 = blockIdx.x * 128;
    int n0 = blockIdx.y * 256;

    float acc[4][8][4];
#pragma unroll
    for (int i = 0; i < 4; i++)
#pragma unroll
        for (int j = 0; j < 8; j++)
#pragma unroll
            for (int k = 0; k < 4; k++) acc[i][j][k] = 0.f;

#define LOAD_H(kc, buf)                                                              \
    do {                                                                             \
        _Pragma("unroll")                                                            \
        for (int i_ = 0; i_ < 6; i_++) {                                             \
            int u_ = tid + i_ * 256;                                                 \
            const __half* src_;                                                      \
            uint32_t sp_;                                                            \
            int grow_, c_;                                                           \
            if (u_ < 512) {                                                          \
                int r_ = u_ >> 2;                                                    \
                c_ = u_ & 3;                                                         \
                src_ = A; grow_ = m0 + r_;                                           \
                sp_ = sb + (buf) * STH + r_ * SRW + c_ * 16;                         \
            } else {                                                                 \
                int v_ = u_ - 512;                                                   \
                int r_ = v_ >> 2;                                                    \
                c_ = v_ & 3;                                                         \
                src_ = B; grow_ = n0 + r_;                                           \
                sp_ = sb + (buf) * STH + AH_OP + r_ * SRW + c_ * 16;                 \
            }                                                                        \
            const void* gp_ = src_ + (size_t)grow_ * EE + (kc) * BK + c_ * 8;        \
            CP_ASYNC16(sp_, gp_);                                                    \
        }                                                                            \
        asm volatile("cp.async.commit_group;");                                      \
    } while (0)

    LOAD_H(0, 0);

    for (int kc = 0; kc < 16; kc++) {
        int buf = kc & 1;
        if (kc < 15) {
            LOAD_H(kc + 1, buf ^ 1);
            asm volatile("cp.async.wait_group 1;");
        } else {
            asm volatile("cp.async.wait_group 0;");
        }
        __syncthreads();

        uint32_t base = sb + buf * STH;
#pragma unroll
        for (int ks = 0; ks < 2; ks++) {
            int kk = ks * 32;
            uint32_t a[4][4];
#pragma unroll
            for (int mi = 0; mi < 4; mi++) {
                uint32_t ra = base + (uint32_t)(wm + mi * 16 + (lane & 15)) * SRW
                            + kk + ((lane >> 4) << 4);
                LDSM4(a[mi], ra);
            }
#pragma unroll
            for (int ni = 0; ni < 8; ni++) {
                uint32_t rb = base + AH_OP
                            + (uint32_t)(wn + ni * 8 + (lane & 7)) * SRW
                            + kk + (((lane >> 3) & 1) << 4);
                uint32_t b[2];
                LDSM2(b, rb);
#pragma unroll
                for (int mi = 0; mi < 4; mi++) MMA_F16(acc[mi][ni], a[mi], b);
            }
        }
        __syncthreads();
    }

#pragma unroll
    for (int ni = 0; ni < 8; ni++) {
        int c0 = n0 + wn + ni * 8 + (lane & 3) * 2;
        float b0 = bias[c0], b1 = bias[c0 + 1];
#pragma unroll
        for (int mi = 0; mi < 4; mi++) {
            int r0 = m0 + wm + mi * 16 + (lane >> 2);
            float* p = C + (size_t)r0 * VV + c0;
            *(float2*)p = make_float2(acc[mi][ni][0] + b0, acc[mi][ni][1] + b1);
            *(float2*)(p + (size_t)8 * VV) =
                make_float2(acc[mi][ni][2] + b0, acc[mi][ni][3] + b1);
        }
    }
}

// ================= fp32 -> fp16 convert =================
__global__ void cvt_f16_kernel(const float* __restrict__ src,
                               __half* __restrict__ dst, int n4) {
    int i = blockIdx.x * blockDim.x + threadIdx.x;
    if (i >= n4) return;
    float4 v = ((const float4*)src)[i];
    ((__half2*)dst)[2 * i + 0] = __floats2half2_rn(v.x, v.y);
    ((__half2*)dst)[2 * i + 1] = __floats2half2_rn(v.z, v.w);
}

// ================= fp32 -> (bf16 hi, bf16 lo) split =================
__global__ void split_kernel(const float* __restrict__ src,
                             __nv_bfloat16* __restrict__ hi,
                             __nv_bfloat16* __restrict__ lo, int n4) {
    int i = blockIdx.x * blockDim.x + threadIdx.x;
    if (i >= n4) return;
    float4 v = ((const float4*)src)[i];
    __nv_bfloat16 h0, h1, h2, h3, l0, l1, l2, l3;
    bf16_split(v.x, h0, l0); bf16_split(v.y, h1, l1);
    bf16_split(v.z, h2, l2); bf16_split(v.w, h3, l3);
    ((__nv_bfloat162*)hi)[2 * i + 0] = __halves2bfloat162(h0, h1);
    ((__nv_bfloat162*)hi)[2 * i + 1] = __halves2bfloat162(h2, h3);
    ((__nv_bfloat162*)lo)[2 * i + 0] = __halves2bfloat162(l0, l1);
    ((__nv_bfloat162*)lo)[2 * i + 1] = __halves2bfloat162(l2, l3);
}

// ================= embedding gather =================
__global__ void gather_kernel(const int* __restrict__ captions,
                              const float* __restrict__ W_emb) {
    int idx = blockIdx.x * blockDim.x + threadIdx.x;
    if (idx >= TT * BB * EE) return;
    int e = idx % EE;
    int b = (idx / EE) % BB;
    int t = idx / (EE * BB);
    float v = W_emb[(size_t)captions[b * TT + t] * EE + e];
    __nv_bfloat16 h, l;
    bf16_split(v, h, l);
    g_Ehi[idx] = h;
    g_Elo[idx] = l;
    if (t == 0) g_SeqH[((size_t)b * TT) * EE + e] = __float2half(v);
}

// ================= h split = 0, c = features, bars = 0 =================
__global__ void init_state_kernel(const float* __restrict__ features) {
    int idx = blockIdx.x * blockDim.x + threadIdx.x;
    if (idx < BB * EE) {
        g_c[idx] = features[idx];
        g_Hhi[idx] = __float2bfloat16(0.f);
        g_Hlo[idx] = __float2bfloat16(0.f);
    }
    if (idx < 64) g_bars[idx] = 0u;
}

// ================= persistent LSTM, v2: 64 CTAs, 1 barrier/step =================
// CTA blk owns cols {g*512 + blk*8 + j : g=0..3, j=0..7} (tile col = g*8+j).
// Per step: full-K 64x32 HMMA rec-GEMM (3-product) -> rec to smem ->
// __syncthreads -> LOCAL pointwise (reads g_xgates + rec, writes c/h/seq)
// -> ONE grid barrier (h ready for next step). No atomics, no xgates writes.
#define SRP 272                    // smem row stride (256B data + 16B pad)
#define HP_OP (64 * SRP)           // 17408 per H operand tile (64 x 128 bf16)
#define WP_OP (32 * SRP)           // 8704 per W operand tile (32 x 128 bf16)
#define STP (2 * HP_OP + 2 * WP_OP)    // 52224 per stage
#define SMP (2 * STP)                  // 104448
#define NCTA 64

__device__ __forceinline__ void gridbar(int slot) {
    __syncthreads();
    __threadfence();
    if (threadIdx.x == 0) {
        atomicAdd(&g_bars[slot], 1u);
        while (*(volatile unsigned*)&g_bars[slot] < (unsigned)NCTA) {}
    }
    __syncthreads();
    __threadfence();
}

__global__ __launch_bounds__(256) void lstm_persist_kernel() {
    extern __shared__ char smem[];
    uint32_t sb = smem_u32(smem);
    float* Rs = (float*)smem;               // [64][33] rec staging (8448 B)
    int blk = blockIdx.x;
    int tid = threadIdx.x;
    int lane = tid & 31, wid = tid >> 5;
    int wm = (wid & 3) * 16;                // warp M offset (batch rows)
    int wn = (wid >> 2) * 16;               // warp N offset (tile cols)

    // stage loader: 3072 16B units (Hhi/Hlo 64x16 each, Whi/Wlo 32x16 each)
#define LOAD_P(kc, buf)                                                              \
    do {                                                                             \
        _Pragma("unroll")                                                            \
        for (int i_ = 0; i_ < 12; i_++) {                                            \
            int u_ = tid + i_ * 256;                                                 \
            const __nv_bfloat16* src_;                                               \
            uint32_t sp_;                                                            \
            int grow_, c_;                                                           \
            if (u_ < 2048) {            /* H tiles */                                 \
                int op_ = u_ >> 10;                                                  \
                int q_ = u_ & 1023;                                                  \
                int r_ = q_ >> 4;                                                    \
                c_ = q_ & 15;                                                        \
                src_ = op_ ? g_Hlo : g_Hhi;                                          \
                grow_ = r_;                                                          \
                sp_ = sb + (buf) * STP + op_ * HP_OP + r_ * SRP + c_ * 16;           \
            } else {                    /* W tiles: row r -> Whh row g*512+blk*8+j */ \
                int v_ = u_ - 2048;                                                  \
                int op_ = v_ >> 9;                                                   \
                int q_ = v_ & 511;                                                   \
                int r_ = q_ >> 4;                                                    \
                c_ = q_ & 15;                                                        \
                src_ = op_ ? g_WhhLo : g_WhhHi;                                      \
                grow_ = (r_ >> 3) * 512 + blk * 8 + (r_ & 7);                        \
                sp_ = sb + (buf) * STP + 2 * HP_OP + op_ * WP_OP + r_ * SRP + c_ * 16; \
            }                                                                        \
            const void* gp_ = src_ + (size_t)grow_ * EE + (kc) * 128 + c_ * 8;       \
            CP_ASYNC16(sp_, gp_);                                                    \
        }                                                                            \
        asm volatile("cp.async.commit_group;");                                      \
    } while (0)

    for (int t = 1; t < TT; t++) {
        float acc[2][4];
#pragma unroll
        for (int i = 0; i < 2; i++)
#pragma unroll
            for (int j = 0; j < 4; j++) acc[i][j] = 0.f;

        if (t > 1) {
            // ---- rec = h @ Whh_slice^T, full K=512 in 4 chunks ----
            LOAD_P(0, 0);
            for (int kc = 0; kc < 4; kc++) {
                int buf = kc & 1;
                if (kc < 3) {
                    LOAD_P(kc + 1, buf ^ 1);
                    asm volatile("cp.async.wait_group 1;");
                } else {
                    asm volatile("cp.async.wait_group 0;");
                }
                __syncthreads();
                uint32_t base = sb + buf * STP;
#pragma unroll
                for (int ks = 0; ks < 8; ks++) {
                    int kk = ks * 32;
                    uint32_t ah[4], al[4];
                    uint32_t ra = base + (uint32_t)(wm + (lane & 15)) * SRP
                                + kk + ((lane >> 4) << 4);
                    LDSM4(ah, ra);
                    LDSM4(al, ra + HP_OP);
#pragma unroll
                    for (int ni = 0; ni < 2; ni++) {
                        uint32_t rb = base + 2 * HP_OP
                                    + (uint32_t)(wn + ni * 8 + (lane & 7)) * SRP
                                    + kk + (((lane >> 3) & 1) << 4);
                        uint32_t bh[2], bl[2];
                        LDSM2(bh, rb);
                        LDSM2(bl, rb + WP_OP);
                        MMA_BF16(acc[ni], ah, bh);
                        MMA_BF16(acc[ni], ah, bl);
                        MMA_BF16(acc[ni], al, bh);
                    }
                }
                __syncthreads();
            }
        }

        // ---- stage rec into smem [64][33] ----
#pragma unroll
        for (int ni = 0; ni < 2; ni++) {
            int c0 = wn + ni * 8 + (lane & 3) * 2;
            int r0 = wm + (lane >> 2);
            Rs[r0 * 33 + c0] = acc[ni][0];
            Rs[r0 * 33 + c0 + 1] = acc[ni][1];
            Rs[(r0 + 8) * 33 + c0] = acc[ni][2];
            Rs[(r0 + 8) * 33 + c0 + 1] = acc[ni][3];
        }
        __syncthreads();

        // ---- pointwise: 2 elements per thread (64 batch x 8 cols) ----
#pragma unroll
        for (int e = 0; e < 2; e++) {
            int idx = tid * 2 + e;              // 0..511
            int b = idx >> 3, j = idx & 7;
            int n = blk * 8 + j;
            const float* gp = g_xgates + ((size_t)(t - 1) * BB + b) * G4 + n;
            float gi = gp[0]      + Rs[b * 33 + j];
            float gf = gp[EE]     + Rs[b * 33 + 8 + j];
            float gg = gp[2 * EE] + Rs[b * 33 + 16 + j];
            float go = gp[3 * EE] + Rs[b * 33 + 24 + j];
            float iv = 1.f / (1.f + expf(-gi));
            float fv = 1.f / (1.f + expf(-gf));
            float gv = tanhf(gg);
            float ov = 1.f / (1.f + expf(-go));
            int ci = b * EE + n;
            float c = fv * g_c[ci] + iv * gv;
            g_c[ci] = c;
            float h = ov * tanhf(c);
            __nv_bfloat16 hh, hl;
            bf16_split(h, hh, hl);
            g_Hhi[ci] = hh;
            g_Hlo[ci] = hl;
            g_SeqH[((size_t)b * TT + t) * EE + n] = __float2half(h);
        }

        if (t < TT - 1) gridbar(t - 1);
        else __syncthreads();
    }
}

// ================= launch =================
extern "C" void kernel_launch(void* const* d_in, const int* in_sizes, int n_in,
                              void* d_out, int out_size) {
    const float* features = (const float*)d_in[0];
    const int*   captions = (const int*)d_in[1];
    const float* W_emb    = (const float*)d_in[2];
    const float* W_out    = (const float*)d_in[3];
    const float* b_out    = (const float*)d_in[4];
    const float* W_ih     = (const float*)d_in[5];
    const float* W_hh     = (const float*)d_in[6];
    const float* b_ih     = (const float*)d_in[7];
    const float* b_hh     = (const float*)d_in[8];
    float* out = (float*)d_out;

    cudaFuncSetAttribute(hmma_gemm_kernel, cudaFuncAttributeMaxDynamicSharedMemorySize, SMEMB);
    cudaFuncSetAttribute(hf16_gemm_kernel, cudaFuncAttributeMaxDynamicSharedMemorySize, SMH);
    cudaFuncSetAttribute(lstm_persist_kernel, cudaFuncAttributeMaxDynamicSharedMemorySize, SMP);

    void *pEhi, *pElo, *pWiH, *pWiL, *pWhH, *pWhL, *pXg, *pSeqH, *pWoH;
    cudaGetSymbolAddress(&pEhi, g_Ehi);
    cudaGetSymbolAddress(&pElo, g_Elo);
    cudaGetSymbolAddress(&pWiH, g_WihHi);
    cudaGetSymbolAddress(&pWiL, g_WihLo);
    cudaGetSymbolAddress(&pWhH, g_WhhHi);
    cudaGetSymbolAddress(&pWhL, g_WhhLo);
    cudaGetSymbolAddress(&pXg, g_xgates);
    cudaGetSymbolAddress(&pSeqH, g_SeqH);
    cudaGetSymbolAddress(&pWoH, g_WoutH);

    gather_kernel<<<(TT * BB * EE + 255) / 256, 256>>>(captions, W_emb);
    init_state_kernel<<<(BB * EE + 255) / 256, 256>>>(features);

    // x-part of all LSTM steps: xgates = emb @ W_ih^T + b_ih + b_hh  (bf16 split)
    split_kernel<<<(G4 * EE / 4 + 255) / 256, 256>>>(W_ih,
        (__nv_bfloat16*)pWiH, (__nv_bfloat16*)pWiL, G4 * EE / 4);
    split_kernel<<<(G4 * EE / 4 + 255) / 256, 256>>>(W_hh,
        (__nv_bfloat16*)pWhH, (__nv_bfloat16*)pWhL, G4 * EE / 4);
    hmma_gemm_kernel<<<dim3((NSTEP * BB + 127) / 128, G4 / 256), 256, SMEMB>>>(
        (const __nv_bfloat16*)pEhi, (const __nv_bfloat16*)pElo,
        (const __nv_bfloat16*)pWiH, (const __nv_bfloat16*)pWiL,
        (float*)pXg, G4, b_ih, b_hh, NSTEP * BB);

    // W_out -> fp16 (independent of LSTM chain)
    cvt_f16_kernel<<<((int)((size_t)VV * EE / 4) + 255) / 256, 256>>>(
        W_out, (__half*)pWoH, (int)((size_t)VV * EE / 4));

    // serial LSTM (recurrent half): 64 CTAs, 1 barrier/step, no atomics
    lstm_persist_kernel<<<NCTA, 256, SMP>>>();

    // projection: out = seq @ W_out^T + b_out  (fp16 single product)
    hf16_gemm_kernel<<<dim3((TT * BB) / 128, VV / 256), 256, SMH>>>(
        (const __half*)pSeqH, (const __half*)pWoH, out, b_out);
}

// round 16
// speedup vs baseline: 1.1058x; 1.1058x over previous
#include <cuda_runtime.h>
#include <cuda_bf16.h>
#include <cuda_fp16.h>
#include <math.h>
#include <stdint.h>

#define BB 64
#define TT 20
#define EE 512
#define VV 32000
#define G4 2048   // 4*EE
#define NSTEP (TT - 1)

// ---------------- scratch (no allocations allowed) ----------------
__device__ float g_c[BB * EE];
__device__ float g_xgates[NSTEP * BB * G4];      // [(t-1)*64+b][4E]
__device__ unsigned g_bars[64];                  // grid-barrier slots (zeroed per call)
__device__ __nv_bfloat16 g_Hhi[BB * EE];         // h split [b][e] (recurrent A operand)
__device__ __nv_bfloat16 g_Hlo[BB * EE];
__device__ __nv_bfloat16 g_WhhHi[G4 * EE];
__device__ __nv_bfloat16 g_WhhLo[G4 * EE];
__device__ __half g_EmbH[TT * BB * EE];          // fp16 emb [t*64+b][e]
__device__ __half g_WihH[G4 * EE];               // fp16 W_ih
__device__ __half g_SeqH[BB * TT * EE];          // fp16 seq [b*20+t][e] (proj A)
__device__ __half g_WoutH[(size_t)VV * EE];      // fp16 W_out (proj B)

// ================= helpers =================
__device__ __forceinline__ uint32_t smem_u32(const void* p) {
    uint32_t a;
    asm("{ .reg .u64 t; cvta.to.shared.u64 t, %1; cvt.u32.u64 %0, t; }" : "=r"(a) : "l"(p));
    return a;
}
__device__ __forceinline__ void bf16_split(float v, __nv_bfloat16& h, __nv_bfloat16& l) {
    h = __float2bfloat16(v);
    l = __float2bfloat16(v - __bfloat162float(h));
}

#define LDSM4(r, a)                                                            \
    asm volatile("ldmatrix.sync.aligned.m8n8.x4.shared.b16 {%0,%1,%2,%3}, [%4];" \
        : "=r"((r)[0]), "=r"((r)[1]), "=r"((r)[2]), "=r"((r)[3]) : "r"(a))
#define LDSM2(r, a)                                                            \
    asm volatile("ldmatrix.sync.aligned.m8n8.x2.shared.b16 {%0,%1}, [%2];"     \
        : "=r"((r)[0]), "=r"((r)[1]) : "r"(a))
#define MMA_BF16(acc, a, b)                                                    \
    asm volatile("mma.sync.aligned.m16n8k16.row.col.f32.bf16.bf16.f32 "        \
        "{%0,%1,%2,%3}, {%4,%5,%6,%7}, {%8,%9}, {%0,%1,%2,%3};"                \
        : "+f"((acc)[0]), "+f"((acc)[1]), "+f"((acc)[2]), "+f"((acc)[3])       \
        : "r"((a)[0]), "r"((a)[1]), "r"((a)[2]), "r"((a)[3]),                  \
          "r"((b)[0]), "r"((b)[1]))
#define MMA_F16(acc, a, b)                                                     \
    asm volatile("mma.sync.aligned.m16n8k16.row.col.f32.f16.f16.f32 "          \
        "{%0,%1,%2,%3}, {%4,%5,%6,%7}, {%8,%9}, {%0,%1,%2,%3};"                \
        : "+f"((acc)[0]), "+f"((acc)[1]), "+f"((acc)[2]), "+f"((acc)[3])       \
        : "r"((a)[0]), "r"((a)[1]), "r"((a)[2]), "r"((a)[3]),                  \
          "r"((b)[0]), "r"((b)[1]))
#define CP_ASYNC16(sp, gp)                                                     \
    asm volatile("cp.async.cg.shared.global [%0], [%1], 16;" :: "r"(sp), "l"(gp))

// ================= fp16 single-product GEMM (projection + xgates) =================
// C[m0:128, n0:256] = A(fp16) @ B^T(fp16) + bias1 (+bias2). K=512 fixed.
// CTA tile 128x256, 8 warps 2x4, warp tile 64x64. Stores guarded by mrows.
#define BK 32
#define SRW 80
#define AH_OP (128 * SRW)            // 10240
#define BH_OP (256 * SRW)            // 20480
#define STH (AH_OP + BH_OP)          // 30720
#define SMH (2 * STH)                // 61440

__global__ __launch_bounds__(256, 1) void hf16_gemm_kernel(
        const __half* __restrict__ A, const __half* __restrict__ B,
        float* __restrict__ C, int ldc,
        const float* __restrict__ bias1, const float* __restrict__ bias2, int mrows) {
    extern __shared__ char smem[];
    uint32_t sb = smem_u32(smem);
    int tid = threadIdx.x, lane = tid & 31, wid = tid >> 5;
    int wm = (wid & 1) * 64;
    int wn = (wid >> 1) * 64;
    int m0 = blockIdx.x * 128;
    int n0 = blockIdx.y * 256;

    float acc[4][8][4];
#pragma unroll
    for (int i = 0; i < 4; i++)
#pragma unroll
        for (int j = 0; j < 8; j++)
#pragma unroll
            for (int k = 0; k < 4; k++) acc[i][j][k] = 0.f;

#define LOAD_H(kc, buf)                                                              \
    do {                                                                             \
        _Pragma("unroll")                                                            \
        for (int i_ = 0; i_ < 6; i_++) {                                             \
            int u_ = tid + i_ * 256;                                                 \
            const __half* src_;                                                      \
            uint32_t sp_;                                                            \
            int grow_, c_;                                                           \
            if (u_ < 512) {                                                          \
                int r_ = u_ >> 2;                                                    \
                c_ = u_ & 3;                                                         \
                src_ = A; grow_ = m0 + r_;                                           \
                sp_ = sb + (buf) * STH + r_ * SRW + c_ * 16;                         \
            } else {                                                                 \
                int v_ = u_ - 512;                                                   \
                int r_ = v_ >> 2;                                                    \
                c_ = v_ & 3;                                                         \
                src_ = B; grow_ = n0 + r_;                                           \
                sp_ = sb + (buf) * STH + AH_OP + r_ * SRW + c_ * 16;                 \
            }                                                                        \
            const void* gp_ = src_ + (size_t)grow_ * EE + (kc) * BK + c_ * 8;        \
            CP_ASYNC16(sp_, gp_);                                                    \
        }                                                                            \
        asm volatile("cp.async.commit_group;");                                      \
    } while (0)

    LOAD_H(0, 0);

    for (int kc = 0; kc < 16; kc++) {
        int buf = kc & 1;
        if (kc < 15) {
            LOAD_H(kc + 1, buf ^ 1);
            asm volatile("cp.async.wait_group 1;");
        } else {
            asm volatile("cp.async.wait_group 0;");
        }
        __syncthreads();

        uint32_t base = sb + buf * STH;
#pragma unroll
        for (int ks = 0; ks < 2; ks++) {
            int kk = ks * 32;
            uint32_t a[4][4];
#pragma unroll
            for (int mi = 0; mi < 4; mi++) {
                uint32_t ra = base + (uint32_t)(wm + mi * 16 + (lane & 15)) * SRW
                            + kk + ((lane >> 4) << 4);
                LDSM4(a[mi], ra);
            }
#pragma unroll
            for (int ni = 0; ni < 8; ni++) {
                uint32_t rb = base + AH_OP
                            + (uint32_t)(wn + ni * 8 + (lane & 7)) * SRW
                            + kk + (((lane >> 3) & 1) << 4);
                uint32_t b[2];
                LDSM2(b, rb);
#pragma unroll
                for (int mi = 0; mi < 4; mi++) MMA_F16(acc[mi][ni], a[mi], b);
            }
        }
        __syncthreads();
    }

#pragma unroll
    for (int ni = 0; ni < 8; ni++) {
        int c0 = n0 + wn + ni * 8 + (lane & 3) * 2;
        float b0 = bias1[c0], b1 = bias1[c0 + 1];
        if (bias2) { b0 += bias2[c0]; b1 += bias2[c0 + 1]; }
#pragma unroll
        for (int mi = 0; mi < 4; mi++) {
            int r0 = m0 + wm + mi * 16 + (lane >> 2);
            float* p = C + (size_t)r0 * ldc + c0;
            if (r0 < mrows)
                *(float2*)p = make_float2(acc[mi][ni][0] + b0, acc[mi][ni][1] + b1);
            if (r0 + 8 < mrows)
                *(float2*)(p + (size_t)8 * ldc) =
                    make_float2(acc[mi][ni][2] + b0, acc[mi][ni][3] + b1);
        }
    }
}

// ================= fp32 -> fp16 convert =================
__global__ void cvt_f16_kernel(const float* __restrict__ src,
                               __half* __restrict__ dst, int n4) {
    int i = blockIdx.x * blockDim.x + threadIdx.x;
    if (i >= n4) return;
    float4 v = ((const float4*)src)[i];
    ((__half2*)dst)[2 * i + 0] = __floats2half2_rn(v.x, v.y);
    ((__half2*)dst)[2 * i + 1] = __floats2half2_rn(v.z, v.w);
}

// ================= fp32 -> (bf16 hi, bf16 lo) split (W_hh only) =================
__global__ void split_kernel(const float* __restrict__ src,
                             __nv_bfloat16* __restrict__ hi,
                             __nv_bfloat16* __restrict__ lo, int n4) {
    int i = blockIdx.x * blockDim.x + threadIdx.x;
    if (i >= n4) return;
    float4 v = ((const float4*)src)[i];
    __nv_bfloat16 h0, h1, h2, h3, l0, l1, l2, l3;
    bf16_split(v.x, h0, l0); bf16_split(v.y, h1, l1);
    bf16_split(v.z, h2, l2); bf16_split(v.w, h3, l3);
    ((__nv_bfloat162*)hi)[2 * i + 0] = __halves2bfloat162(h0, h1);
    ((__nv_bfloat162*)hi)[2 * i + 1] = __halves2bfloat162(h2, h3);
    ((__nv_bfloat162*)lo)[2 * i + 0] = __halves2bfloat162(l0, l1);
    ((__nv_bfloat162*)lo)[2 * i + 1] = __halves2bfloat162(l2, l3);
}

// ================= embedding gather (fp16 emb + seq row 0) =================
__global__ void gather_kernel(const int* __restrict__ captions,
                              const float* __restrict__ W_emb) {
    int idx = blockIdx.x * blockDim.x + threadIdx.x;
    if (idx >= TT * BB * EE) return;
    int e = idx % EE;
    int b = (idx / EE) % BB;
    int t = idx / (EE * BB);
    float v = W_emb[(size_t)captions[b * TT + t] * EE + e];
    __half hv = __float2half(v);
    g_EmbH[idx] = hv;
    if (t == 0) g_SeqH[((size_t)b * TT) * EE + e] = hv;
}

// ================= h split = 0, c = features, bars = 0 =================
__global__ void init_state_kernel(const float* __restrict__ features) {
    int idx = blockIdx.x * blockDim.x + threadIdx.x;
    if (idx < BB * EE) {
        g_c[idx] = features[idx];
        g_Hhi[idx] = __float2bfloat16(0.f);
        g_Hlo[idx] = __float2bfloat16(0.f);
    }
    if (idx < 64) g_bars[idx] = 0u;
}

// ================= persistent LSTM (R14 structure, W resident in smem) =========
// 128 CTAs x 256 thr. CTA owns out tile [64 batch x 64 cols] at n0=(blk&31)*64,
// K slice koff=(blk>>5)*128. W_hh slice (hi+lo) loaded ONCE before the loop;
// per step only H (hi+lo) is loaded. Phase A: HMMA 3-product, atomics into
// g_xgates. Barrier. Phase B: pointwise. Barrier.
#define SRP 272                   // smem row stride (256B data + 16B pad)
#define P_OP (64 * SRP)           // 17408 B per operand tile (64 x 128 bf16)
#define SMP (4 * P_OP)            // 69632: Whi, Wlo, Hhi, Hlo

__device__ __forceinline__ void gridbar(int slot) {
    __syncthreads();
    __threadfence();
    if (threadIdx.x == 0) {
        atomicAdd(&g_bars[slot], 1u);
        while (*(volatile unsigned*)&g_bars[slot] < 128u) {}
    }
    __syncthreads();
    __threadfence();
}

__global__ __launch_bounds__(256) void lstm_persist_kernel() {
    extern __shared__ char smem[];
    uint32_t sb = smem_u32(smem);
    int blk = blockIdx.x;
    int tid = threadIdx.x;
    int lane = tid & 31, wid = tid >> 5;
    int n0 = (blk & 31) * 64;
    int koff = (blk >> 5) * 128;
    int wm = (wid & 3) * 16;        // warp M offset (batch rows)
    int wn = (wid >> 2) * 32;       // warp N offset

    // ---- load W_hh slice (hi+lo, 64 rows x 128 bf16 each) ONCE ----
#pragma unroll
    for (int i = 0; i < 8; i++) {
        int u = tid + i * 256;          // 0..2047 16B units
        int op = u >> 10;               // 0=Whi 1=Wlo
        int q = u & 1023;
        int r = q >> 4;
        int c = q & 15;
        const __nv_bfloat16* src = op ? g_WhhLo : g_WhhHi;
        const void* gp = src + (size_t)(n0 + r) * EE + koff + c * 8;
        CP_ASYNC16(sb + op * P_OP + r * SRP + c * 16, gp);
    }
    asm volatile("cp.async.commit_group;");
    asm volatile("cp.async.wait_group 0;");
    __syncthreads();

    for (int t = 1; t < TT; t++) {
        if (t > 1) {
            // ---- load H (hi+lo, 64 rows x 128 bf16 each) ----
#pragma unroll
            for (int i = 0; i < 8; i++) {
                int u = tid + i * 256;
                int op = u >> 10;           // 0=Hhi 1=Hlo
                int q = u & 1023;
                int r = q >> 4;
                int c = q & 15;
                const __nv_bfloat16* src = op ? g_Hlo : g_Hhi;
                const void* gp = src + (size_t)r * EE + koff + c * 8;
                CP_ASYNC16(sb + (2 + op) * P_OP + r * SRP + c * 16, gp);
            }
            asm volatile("cp.async.commit_group;");
            asm volatile("cp.async.wait_group 0;");
            __syncthreads();

            float acc[4][4];
#pragma unroll
            for (int i = 0; i < 4; i++)
#pragma unroll
                for (int j = 0; j < 4; j++) acc[i][j] = 0.f;

#pragma unroll
            for (int ks = 0; ks < 8; ks++) {
                int kk = ks * 32;
                uint32_t ah[4], al[4];
                uint32_t ra = sb + 2 * P_OP + (uint32_t)(wm + (lane & 15)) * SRP
                            + kk + ((lane >> 4) << 4);
                LDSM4(ah, ra);
                LDSM4(al, ra + P_OP);
#pragma unroll
                for (int ni = 0; ni < 4; ni++) {
                    uint32_t rb = sb
                                + (uint32_t)(wn + ni * 8 + (lane & 7)) * SRP
                                + kk + (((lane >> 3) & 1) << 4);
                    uint32_t bh[2], bl[2];
                    LDSM2(bh, rb);
                    LDSM2(bl, rb + P_OP);
                    MMA_BF16(acc[ni], ah, bh);
                    MMA_BF16(acc[ni], ah, bl);
                    MMA_BF16(acc[ni], al, bh);
                }
            }
            // atomically accumulate into xgates (16 values/thread)
            float* gbase = g_xgates + (size_t)(t - 1) * BB * G4;
#pragma unroll
            for (int ni = 0; ni < 4; ni++) {
                int c0 = n0 + wn + ni * 8 + (lane & 3) * 2;
                int r0 = wm + (lane >> 2);
                atomicAdd(gbase + (size_t)r0 * G4 + c0, acc[ni][0]);
                atomicAdd(gbase + (size_t)r0 * G4 + c0 + 1, acc[ni][1]);
                atomicAdd(gbase + (size_t)(r0 + 8) * G4 + c0, acc[ni][2]);
                atomicAdd(gbase + (size_t)(r0 + 8) * G4 + c0 + 1, acc[ni][3]);
            }
            __syncthreads();   // H smem reusable next step after this CTA is done

            gridbar(2 * (t - 1));
        }

        // ---- phase B: pointwise ----
        {
            int idx = blk * 256 + tid;          // 0..32767
            int bb = idx >> 9, n = idx & 511;
            const float* gp = g_xgates + ((size_t)(t - 1) * BB + bb) * G4 + n;
            float gi = gp[0];
            float gf = gp[EE];
            float gg = gp[2 * EE];
            float go = gp[3 * EE];
            float iv = 1.f / (1.f + expf(-gi));
            float fv = 1.f / (1.f + expf(-gf));
            float gv = tanhf(gg);
            float ov = 1.f / (1.f + expf(-go));
            float c = fv * g_c[idx] + iv * gv;
            g_c[idx] = c;
            float h = ov * tanhf(c);
            __nv_bfloat16 hh, hl;
            bf16_split(h, hh, hl);
            g_Hhi[idx] = hh;                    // idx == bb*512 + n
            g_Hlo[idx] = hl;
            g_SeqH[((size_t)bb * TT + t) * EE + n] = __float2half(h);
        }

        if (t < TT - 1) gridbar(2 * (t - 1) + 1);
    }
}

// ================= launch =================
extern "C" void kernel_launch(void* const* d_in, const int* in_sizes, int n_in,
                              void* d_out, int out_size) {
    const float* features = (const float*)d_in[0];
    const int*   captions = (const int*)d_in[1];
    const float* W_emb    = (const float*)d_in[2];
    const float* W_out    = (const float*)d_in[3];
    const float* b_out    = (const float*)d_in[4];
    const float* W_ih     = (const float*)d_in[5];
    const float* W_hh     = (const float*)d_in[6];
    const float* b_ih     = (const float*)d_in[7];
    const float* b_hh     = (const float*)d_in[8];
    float* out = (float*)d_out;

    cudaFuncSetAttribute(hf16_gemm_kernel, cudaFuncAttributeMaxDynamicSharedMemorySize, SMH);
    cudaFuncSetAttribute(lstm_persist_kernel, cudaFuncAttributeMaxDynamicSharedMemorySize, SMP);

    void *pWhH, *pWhL, *pXg, *pEmbH, *pWiH, *pSeqH, *pWoH;
    cudaGetSymbolAddress(&pWhH, g_WhhHi);
    cudaGetSymbolAddress(&pWhL, g_WhhLo);
    cudaGetSymbolAddress(&pXg, g_xgates);
    cudaGetSymbolAddress(&pEmbH, g_EmbH);
    cudaGetSymbolAddress(&pWiH, g_WihH);
    cudaGetSymbolAddress(&pSeqH, g_SeqH);
    cudaGetSymbolAddress(&pWoH, g_WoutH);

    gather_kernel<<<(TT * BB * EE + 255) / 256, 256>>>(captions, W_emb);
    init_state_kernel<<<(BB * EE + 255) / 256, 256>>>(features);

    // W_ih -> fp16; xgates = emb @ W_ih^T + b_ih + b_hh (fp16 single product)
    cvt_f16_kernel<<<(G4 * EE / 4 + 255) / 256, 256>>>(
        W_ih, (__half*)pWiH, G4 * EE / 4);
    hf16_gemm_kernel<<<dim3((NSTEP * BB + 127) / 128, G4 / 256), 256, SMH>>>(
        (const __half*)pEmbH, (const __half*)pWiH,
        (float*)pXg, G4, b_ih, b_hh, NSTEP * BB);

    // W_hh -> bf16 split (recurrent GEMM stays 3-product)
    split_kernel<<<(G4 * EE / 4 + 255) / 256, 256>>>(W_hh,
        (__nv_bfloat16*)pWhH, (__nv_bfloat16*)pWhL, G4 * EE / 4);

    // W_out -> fp16
    cvt_f16_kernel<<<((int)((size_t)VV * EE / 4) + 255) / 256, 256>>>(
        W_out, (__half*)pWoH, (int)((size_t)VV * EE / 4));

    // serial LSTM (recurrent half), W resident in smem
    lstm_persist_kernel<<<128, 256, SMP>>>();

    // projection: out = seq @ W_out^T + b_out  (fp16 single product)
    hf16_gemm_kernel<<<dim3((TT * BB) / 128, VV / 256), 256, SMH>>>(
        (const __half*)pSeqH, (const __half*)pWoH, out, VV, b_out, nullptr, TT * BB);
}

// round 17
// speedup vs baseline: 1.1067x; 1.0008x over previous
#include <cuda_runtime.h>
#include <cuda_bf16.h>
#include <cuda_fp16.h>
#include <math.h>
#include <stdint.h>

#define BB 64
#define TT 20
#define EE 512
#define VV 32000
#define G4 2048   // 4*EE
#define NSTEP (TT - 1)

// ---------------- scratch (no allocations allowed) ----------------
__device__ float g_c[BB * EE];
__device__ float g_xgates[NSTEP * BB * G4];      // [(t-1)*64+b][4E]
__device__ unsigned g_bars[64];                  // grid-barrier slots (zeroed per call)
__device__ __nv_bfloat16 g_Hhi[BB * EE];         // h split [b][e] (recurrent A operand)
__device__ __nv_bfloat16 g_Hlo[BB * EE];
__device__ __nv_bfloat16 g_WhhHi[G4 * EE];
__device__ __nv_bfloat16 g_WhhLo[G4 * EE];
__device__ __half g_EmbH[TT * BB * EE];          // fp16 emb [t*64+b][e]
__device__ __half g_WihH[G4 * EE];               // fp16 W_ih
__device__ __half g_SeqH[BB * TT * EE];          // fp16 seq [b*20+t][e] (proj A)
__device__ __half g_WoutH[(size_t)VV * EE];      // fp16 W_out (proj B)

// ================= helpers =================
__device__ __forceinline__ uint32_t smem_u32(const void* p) {
    uint32_t a;
    asm("{ .reg .u64 t; cvta.to.shared.u64 t, %1; cvt.u32.u64 %0, t; }" : "=r"(a) : "l"(p));
    return a;
}
__device__ __forceinline__ void bf16_split(float v, __nv_bfloat16& h, __nv_bfloat16& l) {
    h = __float2bfloat16(v);
    l = __float2bfloat16(v - __bfloat162float(h));
}

#define LDSM4(r, a)                                                            \
    asm volatile("ldmatrix.sync.aligned.m8n8.x4.shared.b16 {%0,%1,%2,%3}, [%4];" \
        : "=r"((r)[0]), "=r"((r)[1]), "=r"((r)[2]), "=r"((r)[3]) : "r"(a))
#define LDSM2(r, a)                                                            \
    asm volatile("ldmatrix.sync.aligned.m8n8.x2.shared.b16 {%0,%1}, [%2];"     \
        : "=r"((r)[0]), "=r"((r)[1]) : "r"(a))
#define MMA_BF16(acc, a, b)                                                    \
    asm volatile("mma.sync.aligned.m16n8k16.row.col.f32.bf16.bf16.f32 "        \
        "{%0,%1,%2,%3}, {%4,%5,%6,%7}, {%8,%9}, {%0,%1,%2,%3};"                \
        : "+f"((acc)[0]), "+f"((acc)[1]), "+f"((acc)[2]), "+f"((acc)[3])       \
        : "r"((a)[0]), "r"((a)[1]), "r"((a)[2]), "r"((a)[3]),                  \
          "r"((b)[0]), "r"((b)[1]))
#define MMA_F16(acc, a, b)                                                     \
    asm volatile("mma.sync.aligned.m16n8k16.row.col.f32.f16.f16.f32 "          \
        "{%0,%1,%2,%3}, {%4,%5,%6,%7}, {%8,%9}, {%0,%1,%2,%3};"                \
        : "+f"((acc)[0]), "+f"((acc)[1]), "+f"((acc)[2]), "+f"((acc)[3])       \
        : "r"((a)[0]), "r"((a)[1]), "r"((a)[2]), "r"((a)[3]),                  \
          "r"((b)[0]), "r"((b)[1]))
#define CP_ASYNC16(sp, gp)                                                     \
    asm volatile("cp.async.cg.shared.global [%0], [%1], 16;" :: "r"(sp), "l"(gp))

// ================= fp16 single-product GEMM (projection + xgates) =================
#define BK 32
#define SRW 80
#define AH_OP (128 * SRW)            // 10240
#define BH_OP (256 * SRW)            // 20480
#define STH (AH_OP + BH_OP)          // 30720
#define SMH (2 * STH)                // 61440

__global__ __launch_bounds__(256, 1) void hf16_gemm_kernel(
        const __half* __restrict__ A, const __half* __restrict__ B,
        float* __restrict__ C, int ldc,
        const float* __restrict__ bias1, const float* __restrict__ bias2, int mrows) {
    extern __shared__ char smem[];
    uint32_t sb = smem_u32(smem);
    int tid = threadIdx.x, lane = tid & 31, wid = tid >> 5;
    int wm = (wid & 1) * 64;
    int wn = (wid >> 1) * 64;
    int m0 = blockIdx.x * 128;
    int n0 = blockIdx.y * 256;

    float acc[4][8][4];
#pragma unroll
    for (int i = 0; i < 4; i++)
#pragma unroll
        for (int j = 0; j < 8; j++)
#pragma unroll
            for (int k = 0; k < 4; k++) acc[i][j][k] = 0.f;

#define LOAD_H(kc, buf)                                                              \
    do {                                                                             \
        _Pragma("unroll")                                                            \
        for (int i_ = 0; i_ < 6; i_++) {                                             \
            int u_ = tid + i_ * 256;                                                 \
            const __half* src_;                                                      \
            uint32_t sp_;                                                            \
            int grow_, c_;                                                           \
            if (u_ < 512) {                                                          \
                int r_ = u_ >> 2;                                                    \
                c_ = u_ & 3;                                                         \
                src_ = A; grow_ = m0 + r_;                                           \
                sp_ = sb + (buf) * STH + r_ * SRW + c_ * 16;                         \
            } else {                                                                 \
                int v_ = u_ - 512;                                                   \
                int r_ = v_ >> 2;                                                    \
                c_ = v_ & 3;                                                         \
                src_ = B; grow_ = n0 + r_;                                           \
                sp_ = sb + (buf) * STH + AH_OP + r_ * SRW + c_ * 16;                 \
            }                                                                        \
            const void* gp_ = src_ + (size_t)grow_ * EE + (kc) * BK + c_ * 8;        \
            CP_ASYNC16(sp_, gp_);                                                    \
        }                                                                            \
        asm volatile("cp.async.commit_group;");                                      \
    } while (0)

    LOAD_H(0, 0);

    for (int kc = 0; kc < 16; kc++) {
        int buf = kc & 1;
        if (kc < 15) {
            LOAD_H(kc + 1, buf ^ 1);
            asm volatile("cp.async.wait_group 1;");
        } else {
            asm volatile("cp.async.wait_group 0;");
        }
        __syncthreads();

        uint32_t base = sb + buf * STH;
#pragma unroll
        for (int ks = 0; ks < 2; ks++) {
            int kk = ks * 32;
            uint32_t a[4][4];
#pragma unroll
            for (int mi = 0; mi < 4; mi++) {
                uint32_t ra = base + (uint32_t)(wm + mi * 16 + (lane & 15)) * SRW
                            + kk + ((lane >> 4) << 4);
                LDSM4(a[mi], ra);
            }
#pragma unroll
            for (int ni = 0; ni < 8; ni++) {
                uint32_t rb = base + AH_OP
                            + (uint32_t)(wn + ni * 8 + (lane & 7)) * SRW
                            + kk + (((lane >> 3) & 1) << 4);
                uint32_t b[2];
                LDSM2(b, rb);
#pragma unroll
                for (int mi = 0; mi < 4; mi++) MMA_F16(acc[mi][ni], a[mi], b);
            }
        }
        __syncthreads();
    }

#pragma unroll
    for (int ni = 0; ni < 8; ni++) {
        int c0 = n0 + wn + ni * 8 + (lane & 3) * 2;
        float b0 = bias1[c0], b1 = bias1[c0 + 1];
        if (bias2) { b0 += bias2[c0]; b1 += bias2[c0 + 1]; }
#pragma unroll
        for (int mi = 0; mi < 4; mi++) {
            int r0 = m0 + wm + mi * 16 + (lane >> 2);
            float* p = C + (size_t)r0 * ldc + c0;
            if (r0 < mrows)
                *(float2*)p = make_float2(acc[mi][ni][0] + b0, acc[mi][ni][1] + b1);
            if (r0 + 8 < mrows)
                *(float2*)(p + (size_t)8 * ldc) =
                    make_float2(acc[mi][ni][2] + b0, acc[mi][ni][3] + b1);
        }
    }
}

// ================= fp32 -> fp16 convert =================
__global__ void cvt_f16_kernel(const float* __restrict__ src,
                               __half* __restrict__ dst, int n4) {
    int i = blockIdx.x * blockDim.x + threadIdx.x;
    if (i >= n4) return;
    float4 v = ((const float4*)src)[i];
    ((__half2*)dst)[2 * i + 0] = __floats2half2_rn(v.x, v.y);
    ((__half2*)dst)[2 * i + 1] = __floats2half2_rn(v.z, v.w);
}

// ================= fp32 -> (bf16 hi, bf16 lo) split (W_hh only) =================
__global__ void split_kernel(const float* __restrict__ src,
                             __nv_bfloat16* __restrict__ hi,
                             __nv_bfloat16* __restrict__ lo, int n4) {
    int i = blockIdx.x * blockDim.x + threadIdx.x;
    if (i >= n4) return;
    float4 v = ((const float4*)src)[i];
    __nv_bfloat16 h0, h1, h2, h3, l0, l1, l2, l3;
    bf16_split(v.x, h0, l0); bf16_split(v.y, h1, l1);
    bf16_split(v.z, h2, l2); bf16_split(v.w, h3, l3);
    ((__nv_bfloat162*)hi)[2 * i + 0] = __halves2bfloat162(h0, h1);
    ((__nv_bfloat162*)hi)[2 * i + 1] = __halves2bfloat162(h2, h3);
    ((__nv_bfloat162*)lo)[2 * i + 0] = __halves2bfloat162(l0, l1);
    ((__nv_bfloat162*)lo)[2 * i + 1] = __halves2bfloat162(l2, l3);
}

// ================= gather + state init (fused) =================
__global__ void gather_kernel(const int* __restrict__ captions,
                              const float* __restrict__ W_emb,
                              const float* __restrict__ features) {
    int idx = blockIdx.x * blockDim.x + threadIdx.x;
    if (idx >= TT * BB * EE) return;
    int e = idx % EE;
    int b = (idx / EE) % BB;
    int t = idx / (EE * BB);
    float v = W_emb[(size_t)captions[b * TT + t] * EE + e];
    __half hv = __float2half(v);
    g_EmbH[idx] = hv;
    if (t == 0) g_SeqH[((size_t)b * TT) * EE + e] = hv;
    if (idx < BB * EE) {
        g_c[idx] = features[idx];
        g_Hhi[idx] = __float2bfloat16(0.f);
        g_Hlo[idx] = __float2bfloat16(0.f);
    }
    if (idx < 64) g_bars[idx] = 0u;
}

// ================= persistent LSTM (W resident in smem, lean barrier) =========
#define SRP 272                   // smem row stride (256B data + 16B pad)
#define P_OP (64 * SRP)           // 17408 B per operand tile (64 x 128 bf16)
#define SMP (4 * P_OP)            // 69632: Whi, Wlo, Hhi, Hlo

// Lean grid barrier: cooperative-groups pattern, fences only in tid 0.
__device__ __forceinline__ void gridbar(int slot) {
    __syncthreads();
    if (threadIdx.x == 0) {
        __threadfence();                       // release (orders CTA's writes)
        atomicAdd(&g_bars[slot], 1u);
        while (*(volatile unsigned*)&g_bars[slot] < 128u) {}
        __threadfence();                       // acquire
    }
    __syncthreads();
}

__global__ __launch_bounds__(256) void lstm_persist_kernel() {
    extern __shared__ char smem[];
    uint32_t sb = smem_u32(smem);
    int blk = blockIdx.x;
    int tid = threadIdx.x;
    int lane = tid & 31, wid = tid >> 5;
    int n0 = (blk & 31) * 64;
    int koff = (blk >> 5) * 128;
    int wm = (wid & 3) * 16;        // warp M offset (batch rows)
    int wn = (wid >> 2) * 32;       // warp N offset

    // ---- load W_hh slice (hi+lo, 64 rows x 128 bf16 each) ONCE ----
#pragma unroll
    for (int i = 0; i < 8; i++) {
        int u = tid + i * 256;          // 0..2047 16B units
        int op = u >> 10;               // 0=Whi 1=Wlo
        int q = u & 1023;
        int r = q >> 4;
        int c = q & 15;
        const __nv_bfloat16* src = op ? g_WhhLo : g_WhhHi;
        const void* gp = src + (size_t)(n0 + r) * EE + koff + c * 8;
        CP_ASYNC16(sb + op * P_OP + r * SRP + c * 16, gp);
    }
    asm volatile("cp.async.commit_group;");
    asm volatile("cp.async.wait_group 0;");
    __syncthreads();

    for (int t = 1; t < TT; t++) {
        if (t > 1) {
            // ---- load H (hi+lo, 64 rows x 128 bf16 each) ----
#pragma unroll
            for (int i = 0; i < 8; i++) {
                int u = tid + i * 256;
                int op = u >> 10;           // 0=Hhi 1=Hlo
                int q = u & 1023;
                int r = q >> 4;
                int c = q & 15;
                const __nv_bfloat16* src = op ? g_Hlo : g_Hhi;
                const void* gp = src + (size_t)r * EE + koff + c * 8;
                CP_ASYNC16(sb + (2 + op) * P_OP + r * SRP + c * 16, gp);
            }
            asm volatile("cp.async.commit_group;");
            asm volatile("cp.async.wait_group 0;");
            __syncthreads();

            float acc[4][4];
#pragma unroll
            for (int i = 0; i < 4; i++)
#pragma unroll
                for (int j = 0; j < 4; j++) acc[i][j] = 0.f;

#pragma unroll
            for (int ks = 0; ks < 8; ks++) {
                int kk = ks * 32;
                uint32_t ah[4], al[4];
                uint32_t ra = sb + 2 * P_OP + (uint32_t)(wm + (lane & 15)) * SRP
                            + kk + ((lane >> 4) << 4);
                LDSM4(ah, ra);
                LDSM4(al, ra + P_OP);
#pragma unroll
                for (int ni = 0; ni < 4; ni++) {
                    uint32_t rb = sb
                                + (uint32_t)(wn + ni * 8 + (lane & 7)) * SRP
                                + kk + (((lane >> 3) & 1) << 4);
                    uint32_t bh[2], bl[2];
                    LDSM2(bh, rb);
                    LDSM2(bl, rb + P_OP);
                    MMA_BF16(acc[ni], ah, bh);
                    MMA_BF16(acc[ni], ah, bl);
                    MMA_BF16(acc[ni], al, bh);
                }
            }
            // atomically accumulate into xgates (16 values/thread)
            float* gbase = g_xgates + (size_t)(t - 1) * BB * G4;
#pragma unroll
            for (int ni = 0; ni < 4; ni++) {
                int c0 = n0 + wn + ni * 8 + (lane & 3) * 2;
                int r0 = wm + (lane >> 2);
                atomicAdd(gbase + (size_t)r0 * G4 + c0, acc[ni][0]);
                atomicAdd(gbase + (size_t)r0 * G4 + c0 + 1, acc[ni][1]);
                atomicAdd(gbase + (size_t)(r0 + 8) * G4 + c0, acc[ni][2]);
                atomicAdd(gbase + (size_t)(r0 + 8) * G4 + c0 + 1, acc[ni][3]);
            }
            __syncthreads();   // H smem reusable next step once CTA passes here

            gridbar(2 * (t - 1));
        }

        // ---- phase B: pointwise ----
        {
            int idx = blk * 256 + tid;          // 0..32767
            int bb = idx >> 9, n = idx & 511;
            const float* gp = g_xgates + ((size_t)(t - 1) * BB + bb) * G4 + n;
            float gi = gp[0];
            float gf = gp[EE];
            float gg = gp[2 * EE];
            float go = gp[3 * EE];
            float iv = 1.f / (1.f + expf(-gi));
            float fv = 1.f / (1.f + expf(-gf));
            float gv = tanhf(gg);
            float ov = 1.f / (1.f + expf(-go));
            float c = fv * g_c[idx] + iv * gv;
            g_c[idx] = c;
            float h = ov * tanhf(c);
            __nv_bfloat16 hh, hl;
            bf16_split(h, hh, hl);
            g_Hhi[idx] = hh;                    // idx == bb*512 + n
            g_Hlo[idx] = hl;
            g_SeqH[((size_t)bb * TT + t) * EE + n] = __float2half(h);
        }

        if (t < TT - 1) gridbar(2 * (t - 1) + 1);
    }
}

// ================= launch =================
extern "C" void kernel_launch(void* const* d_in, const int* in_sizes, int n_in,
                              void* d_out, int out_size) {
    const float* features = (const float*)d_in[0];
    const int*   captions = (const int*)d_in[1];
    const float* W_emb    = (const float*)d_in[2];
    const float* W_out    = (const float*)d_in[3];
    const float* b_out    = (const float*)d_in[4];
    const float* W_ih     = (const float*)d_in[5];
    const float* W_hh     = (const float*)d_in[6];
    const float* b_ih     = (const float*)d_in[7];
    const float* b_hh     = (const float*)d_in[8];
    float* out = (float*)d_out;

    cudaFuncSetAttribute(hf16_gemm_kernel, cudaFuncAttributeMaxDynamicSharedMemorySize, SMH);
    cudaFuncSetAttribute(lstm_persist_kernel, cudaFuncAttributeMaxDynamicSharedMemorySize, SMP);

    void *pWhH, *pWhL, *pXg, *pEmbH, *pWiH, *pSeqH, *pWoH;
    cudaGetSymbolAddress(&pWhH, g_WhhHi);
    cudaGetSymbolAddress(&pWhL, g_WhhLo);
    cudaGetSymbolAddress(&pXg, g_xgates);
    cudaGetSymbolAddress(&pEmbH, g_EmbH);
    cudaGetSymbolAddress(&pWiH, g_WihH);
    cudaGetSymbolAddress(&pSeqH, g_SeqH);
    cudaGetSymbolAddress(&pWoH, g_WoutH);

    // gather + init fused
    gather_kernel<<<(TT * BB * EE + 255) / 256, 256>>>(captions, W_emb, features);

    // W_ih -> fp16; xgates = emb @ W_ih^T + b_ih + b_hh (fp16 single product)
    cvt_f16_kernel<<<(G4 * EE / 4 + 255) / 256, 256>>>(
        W_ih, (__half*)pWiH, G4 * EE / 4);
    hf16_gemm_kernel<<<dim3((NSTEP * BB + 127) / 128, G4 / 256), 256, SMH>>>(
        (const __half*)pEmbH, (const __half*)pWiH,
        (float*)pXg, G4, b_ih, b_hh, NSTEP * BB);

    // W_hh -> bf16 split (recurrent GEMM stays 3-product)
    split_kernel<<<(G4 * EE / 4 + 255) / 256, 256>>>(W_hh,
        (__nv_bfloat16*)pWhH, (__nv_bfloat16*)pWhL, G4 * EE / 4);

    // W_out -> fp16
    cvt_f16_kernel<<<((int)((size_t)VV * EE / 4) + 255) / 256, 256>>>(
        W_out, (__half*)pWoH, (int)((size_t)VV * EE / 4));

    // serial LSTM (recurrent half), W resident in smem, lean barriers
    lstm_persist_kernel<<<128, 256, SMP>>>();

    // projection: out = seq @ W_out^T + b_out  (fp16 single product)
    hf16_gemm_kernel<<<dim3((TT * BB) / 128, VV / 256), 256, SMH>>>(
        (const __half*)pSeqH, (const __half*)pWoH, out, VV, b_out, nullptr, TT * BB);
}